// round 5
// baseline (speedup 1.0000x reference)
#include <cuda_runtime.h>
#include <cuda_fp16.h>
#include <cstdint>

// ============================================================
// FFTEmbedding as implicit-im2col GEMM (sm_100 legacy-HMMA path)
//   out = A(131072x256 Toeplitz windows) @ WeffT(512x256)^T + bias
// R5: SSA av[47] (no register shifts), double-buffered ldmatrix,
//     cp.async segment prefetch. Target: cut non-HMMA issue slots.
// ============================================================

#define B_SZ   16
#define T_SZ   8192
#define W_SZ   256
#define EMB    512
#define NFEAT  258

#define BM 128
#define BN 128
#define MTILES 1024           // (B*T)/BM
#define GRID   296            // 2 CTAs per SM
#define CTAS_PER_N 74         // GRID / 4 N-tiles
#define THREADS 256

#define PB 264                // B smem pitch in halfs (256 + 8 pad)
#define SMEM_B_BYTES (128 * PB * 2)            // 67584
#define SMEM_TOTAL   (SMEM_B_BYTES + 2 * 384 * 4)

// fp16 Weff^T, [EMB][W_SZ]
__device__ __half g_weffT[EMB * W_SZ];

__device__ __forceinline__ uint32_t smem_to_u32(const void* p) {
    uint32_t a;
    asm("{ .reg .u64 t; cvta.to.shared.u64 t, %1; cvt.u32.u64 %0, t; }" : "=r"(a) : "l"(p));
    return a;
}

__device__ __forceinline__ uint32_t ldcvt(const float* s) {
    __half2 h = __floats2half2_rn(s[0], s[1]);
    return *reinterpret_cast<uint32_t*>(&h);
}

__device__ __forceinline__ void cp_async4(uint32_t dst, const float* src, int sz) {
    asm volatile("cp.async.ca.shared.global [%0], [%1], 4, %2;"
                 :: "r"(dst), "l"(src), "r"(sz) : "memory");
}

__device__ __forceinline__ void cp_async_wait_all() {
    asm volatile("cp.async.wait_all;" ::: "memory");
}

__device__ __forceinline__ void mma16816(float* c, uint32_t a0, uint32_t a1,
                                         uint32_t a2, uint32_t a3,
                                         uint32_t b0, uint32_t b1) {
    asm volatile(
        "mma.sync.aligned.m16n8k16.row.col.f32.f16.f16.f32 "
        "{%0,%1,%2,%3}, {%4,%5,%6,%7}, {%8,%9}, {%0,%1,%2,%3};"
        : "+f"(c[0]), "+f"(c[1]), "+f"(c[2]), "+f"(c[3])
        : "r"(a0), "r"(a1), "r"(a2), "r"(a3), "r"(b0), "r"(b1));
}

__device__ __forceinline__ void ldmatrix_x4(uint32_t& r0, uint32_t& r1,
                                            uint32_t& r2, uint32_t& r3, uint32_t addr) {
    asm volatile("ldmatrix.sync.aligned.m8n8.x4.shared.b16 {%0,%1,%2,%3}, [%4];"
                 : "=r"(r0), "=r"(r1), "=r"(r2), "=r"(r3) : "r"(addr));
}

// Column permutation within each warp's 16-col slice (enables STG.128).
__device__ __host__ __forceinline__ int permcol(int s) {
    return (s < 8) ? ((s & 1) ? 2 * s - 1 : 2 * s)
                   : ((s & 1) ? 2 * s - 15 : 2 * s - 14);
}

// ============================================================
// Kernel 1: Weff^T precompute (angle recurrence)
// ============================================================
__global__ void weff_kernel(const float* __restrict__ weight) {
    __shared__ float w1[129], w2[129];
    const int e = blockIdx.x;
    for (int f = threadIdx.x; f < NFEAT; f += 256) {
        float v = weight[e * NFEAT + f];
        if (f < 129) w1[f] = v; else w2[f - 129] = v;
    }
    __syncthreads();
    const int n = threadIdx.x;                // k position 0..255
    float s1, c1;
    sincospif((float)n / 128.0f, &s1, &c1);   // step angle 2*pi*n/256
    float acc = w1[0];
    float c = c1, s = s1;
    #pragma unroll 4
    for (int kk = 1; kk <= 128; kk++) {
        acc = fmaf(c, w1[kk], acc);
        acc = fmaf(-s, w2[kk], acc);
        float cn = fmaf(c, c1, -s * s1);
        float sn = fmaf(s, c1,  c * s1);
        c = cn; s = sn;
    }
    g_weffT[e * W_SZ + n] = __float2half_rn(acc);
}

// ============================================================
// Kernel 2: persistent GEMM, grid=296 (2 CTAs/SM), 256 threads
// warp tile: 128m x 16n
// ============================================================
__global__ void __launch_bounds__(THREADS, 2) fft_gemm_kernel(
    const float* __restrict__ x,
    const float* __restrict__ bias,
    float* __restrict__ out)
{
    extern __shared__ char smem[];
    __half* Bs = (__half*)smem;
    float (*seg)[384] = (float(*)[384])(smem + SMEM_B_BYTES);

    const int tid  = threadIdx.x;
    const int wid  = tid >> 5;
    const int lane = tid & 31;
    const int q    = lane & 3;
    const int r4   = lane >> 2;
    const int ntile = (int)(blockIdx.x & 3);
    const int e0    = ntile * BN;

    // ---- load B tile (WeffT rows e0..e0+127), permuted within slices ----
    for (int u = tid; u < 4096; u += THREADS) {
        int r  = u >> 5;
        int ch = u & 31;
        int esrc = e0 + (r & ~15) + permcol(r & 15);
        uint4 v = *reinterpret_cast<const uint4*>(&g_weffT[esrc * W_SZ + ch * 8]);
        *reinterpret_cast<uint4*>(Bs + r * PB + ch * 8) = v;
    }

    // ---- per-thread bias: 4 contiguous cols ----
    const int colb = e0 + wid * 16 + 4 * q;
    const float4 bias4 = *reinterpret_cast<const float4*>(bias + colb);

    // ---- ldmatrix base address for this warp's 16-row B slice ----
    const uint32_t sbB = smem_to_u32(Bs);
    const int brow = wid * 16 + (lane & 7) + ((lane & 16) ? 8 : 0);
    const int bkof = (lane & 8) ? 8 : 0;
    const uint32_t baddr0 = sbB + (uint32_t)(brow * PB + bkof) * 2u;

    const uint32_t seg_sm[2] = { smem_to_u32(seg[0]), smem_to_u32(seg[1]) };

    // ---- initial segment load for first M-tile ----
    const int mt0 = (int)(blockIdx.x >> 2);
    {
        int bidx = mt0 >> 6, t0 = (mt0 & 63) * BM;
        int gx0 = t0 + tid - (W_SZ - 1);
        seg[0][tid] = (gx0 >= 0) ? x[bidx * T_SZ + gx0] : 0.0f;
        if (tid < 128) {
            int j = 256 + tid;
            int gx1 = t0 + j - (W_SZ - 1);
            seg[0][j] = (j < 383 && gx1 >= 0) ? x[bidx * T_SZ + gx1] : 0.0f;
        }
    }
    __syncthreads();

    int pb = 0;
    for (int mt = mt0; mt < MTILES; mt += CTAS_PER_N, pb ^= 1) {
        // ---- async prefetch of next segment into alternate buffer ----
        const int mtn = mt + CTAS_PER_N;
        if (mtn < MTILES) {
            int bidx = mtn >> 6, t0 = (mtn & 63) * BM;
            const float* xb = x + bidx * T_SZ;
            int gx0 = t0 + tid - (W_SZ - 1);
            cp_async4(seg_sm[pb ^ 1] + tid * 4u,
                      xb + max(gx0, 0), gx0 >= 0 ? 4 : 0);
            if (tid < 128) {
                int j = 256 + tid;
                int gx1 = t0 + j - (W_SZ - 1);
                cp_async4(seg_sm[pb ^ 1] + j * 4u,
                          xb + max(gx1, 0), (j < 383 && gx1 >= 0) ? 4 : 0);
            }
        }

        // ---- MMA mainloop: K=256 (16 k-steps), 8 m-tiles, 2 n-tiles ----
        float acc[8][2][4];
        #pragma unroll
        for (int m = 0; m < 8; m++)
            #pragma unroll
            for (int n = 0; n < 2; n++)
                #pragma unroll
                for (int c = 0; c < 4; c++) acc[m][n][c] = 0.0f;

        const float* sg = seg[pb];
        const int base0 = r4 + 2 * q;

        // Toeplitz A values, write-once SSA: av[i] = half2(sg[base0+8i..+1])
        uint32_t av[47];
        #pragma unroll
        for (int i = 0; i < 17; i++) av[i] = ldcvt(sg + base0 + 8 * i);

        // double-buffered B fragments
        uint32_t bf[2][4];
        ldmatrix_x4(bf[0][0], bf[0][1], bf[0][2], bf[0][3], baddr0);

        #pragma unroll
        for (int ks = 0; ks < 16; ks++) {
            const int cur = ks & 1;
            if (ks < 15) {
                // prefetch next B frags + next two A values before this
                // step's HMMA block (hide LDS/LDSM latency)
                ldmatrix_x4(bf[cur ^ 1][0], bf[cur ^ 1][1],
                            bf[cur ^ 1][2], bf[cur ^ 1][3],
                            baddr0 + (uint32_t)((ks + 1) * 32));
                av[2 * ks + 17] = ldcvt(sg + base0 + 8 * (2 * ks + 17));
                av[2 * ks + 18] = ldcvt(sg + base0 + 8 * (2 * ks + 18));
            }
            #pragma unroll
            for (int m = 0; m < 8; m++) {
                const int i0 = 2 * ks + 2 * m;
                mma16816(acc[m][0], av[i0], av[i0 + 1], av[i0 + 1], av[i0 + 2],
                         bf[cur][0], bf[cur][1]);
                mma16816(acc[m][1], av[i0], av[i0 + 1], av[i0 + 1], av[i0 + 2],
                         bf[cur][2], bf[cur][3]);
            }
        }

        // ---- epilogue: bias + STG.128 (permuted cols contiguous) ----
        const size_t rowb = (size_t)mt * BM + (size_t)r4;
        #pragma unroll
        for (int m = 0; m < 8; m++) {
            float* o0 = out + (rowb + 16 * m) * EMB + colb;
            float* o1 = o0 + 8 * EMB;
            float4 v0 = make_float4(acc[m][0][0] + bias4.x, acc[m][0][1] + bias4.y,
                                    acc[m][1][0] + bias4.z, acc[m][1][1] + bias4.w);
            float4 v1 = make_float4(acc[m][0][2] + bias4.x, acc[m][0][3] + bias4.y,
                                    acc[m][1][2] + bias4.z, acc[m][1][3] + bias4.w);
            *reinterpret_cast<float4*>(o0) = v0;
            *reinterpret_cast<float4*>(o1) = v1;
        }
        cp_async_wait_all();
        __syncthreads();   // next seg visible; old seg free
    }
}

// ============================================================
extern "C" void kernel_launch(void* const* d_in, const int* in_sizes, int n_in,
                              void* d_out, int out_size) {
    const float* x  = nullptr;
    const float* wt = nullptr;
    const float* bs = nullptr;
    for (int i = 0; i < n_in; i++) {
        if (in_sizes[i] == B_SZ * T_SZ)        x  = (const float*)d_in[i];
        else if (in_sizes[i] == EMB * NFEAT)   wt = (const float*)d_in[i];
        else if (in_sizes[i] == EMB)           bs = (const float*)d_in[i];
    }

    weff_kernel<<<EMB, 256>>>(wt);

    cudaFuncSetAttribute(fft_gemm_kernel,
                         cudaFuncAttributeMaxDynamicSharedMemorySize, SMEM_TOTAL);
    fft_gemm_kernel<<<GRID, THREADS, SMEM_TOTAL>>>(x, bs, (float*)d_out);
}